// round 4
// baseline (speedup 1.0000x reference)
#include <cuda_runtime.h>
#include <cuda_bf16.h>
#include <math.h>

// Shapes (fixed by the problem)
#define BB 64      // batch
#define TT 512     // seq len
#define EE 256     // embed dim
#define HH 512     // hidden
#define G3 1536    // 3*H

// ---------------- scratch (device globals; no allocation allowed) ------------
__device__ float g_x0[(size_t)BB * TT * EE];             // [B*T][256]   embeddings
__device__ float g_xg[(size_t)2 * TT * BB * G3];         // [dir][t][b][3H] input-gate proj (reused both layers)
__device__ float g_out0[(size_t)BB * TT * 2 * HH];       // [b][t][2H]   layer-0 outputs
__device__ float g_h[(size_t)2 * 2 * BB * HH];           // [dir][buf][b][H] ping-pong state
__device__ unsigned g_bar_count = 0;
__device__ volatile unsigned g_bar_gen = 0;

// ---------------- software grid barrier (all CTAs co-resident: grid=128<=148 SMs)
__device__ __forceinline__ void grid_sync(unsigned nblocks) {
    __threadfence();
    __syncthreads();
    if (threadIdx.x == 0) {
        unsigned my = g_bar_gen;
        if (atomicAdd(&g_bar_count, 1) == nblocks - 1) {
            atomicExch(&g_bar_count, 0);
            __threadfence();
            g_bar_gen = my + 1;
        } else {
            while (g_bar_gen == my) __nanosleep(64);
        }
    }
    __syncthreads();
    __threadfence();
}

// ---------------- embedding gather ----------------
__global__ void embed_kernel(const int* __restrict__ sent, const float* __restrict__ emb) {
    int row = blockIdx.x;                 // row = b*T + t
    int idx = sent[row];
    const float4* src = (const float4*)(emb + (size_t)idx * EE);
    float4* dst = (float4*)(g_x0 + (size_t)row * EE);
    dst[threadIdx.x] = src[threadIdx.x];  // 64 threads * float4 = 256 floats
}

// ---------------- input projection GEMM: xg[dir][t][b][g] = A[b*T+t][:] . W[dir][g][:] + b_ih
// A = g_x0 (layer0, K=256) or g_out0 (layer1, K=1024). Tile 64x64, BK=16, 4x4 microtile.
__global__ __launch_bounds__(256) void inproj_kernel(const float* __restrict__ W,
                                                     const float* __restrict__ bias,
                                                     int K, int layer) {
    const float* A = (layer == 0) ? g_x0 : g_out0;
    __shared__ float As[16][64];
    __shared__ float Bs[16][64];
    const int m0 = blockIdx.x * 64, n0 = blockIdx.y * 64, dir = blockIdx.z;
    const float* Wd = W + (size_t)dir * G3 * K;
    const int tid = threadIdx.x;
    const int lr = tid >> 2, lc = tid & 3;     // loader: row 0..63, float4 col 0..3
    const int ty = tid >> 4, tx = tid & 15;    // compute: 16x16 threads, 4x4 outputs
    float acc[4][4] = {};

    for (int k0 = 0; k0 < K; k0 += 16) {
        float4 av = *(const float4*)(A + (size_t)(m0 + lr) * K + k0 + lc * 4);
        float4 bv = *(const float4*)(Wd + (size_t)(n0 + lr) * K + k0 + lc * 4);
        As[lc*4+0][lr]=av.x; As[lc*4+1][lr]=av.y; As[lc*4+2][lr]=av.z; As[lc*4+3][lr]=av.w;
        Bs[lc*4+0][lr]=bv.x; Bs[lc*4+1][lr]=bv.y; Bs[lc*4+2][lr]=bv.z; Bs[lc*4+3][lr]=bv.w;
        __syncthreads();
        #pragma unroll
        for (int k = 0; k < 16; k++) {
            float4 a4 = *(const float4*)&As[k][ty * 4];
            float4 b4 = *(const float4*)&Bs[k][tx * 4];
            float a[4] = {a4.x, a4.y, a4.z, a4.w};
            float b[4] = {b4.x, b4.y, b4.z, b4.w};
            #pragma unroll
            for (int i = 0; i < 4; i++)
                #pragma unroll
                for (int j = 0; j < 4; j++)
                    acc[i][j] = fmaf(a[i], b[j], acc[i][j]);
        }
        __syncthreads();
    }
    const float* bs = bias + dir * G3 + n0 + tx * 4;
    float b0 = bs[0], b1 = bs[1], b2 = bs[2], b3 = bs[3];
    #pragma unroll
    for (int i = 0; i < 4; i++) {
        int m = m0 + ty * 4 + i;
        int bb = m >> 9, t = m & 511;          // m = b*512 + t
        float* dst = g_xg + (((size_t)dir * TT + t) * BB + bb) * G3 + n0 + tx * 4;
        float4 o;
        o.x = acc[i][0] + b0; o.y = acc[i][1] + b1; o.z = acc[i][2] + b2; o.w = acc[i][3] + b3;
        *(float4*)dst = o;
    }
}

// ---------------- persistent GRU scan (one launch per layer) ----------------
// grid = 128 CTAs: dir(2) x bhalf(2: 32 batches) x ublk(32: 16 units).
// warp w -> 2 units (6 w_hh rows, register-resident all 512 steps).
__global__ __launch_bounds__(256) void scan_kernel(const float* __restrict__ w_hh,
                                                   const float* __restrict__ b_hh,
                                                   int layer) {
    extern __shared__ float hs[];  // [32][512] = 64KB staged h_old (this CTA's 32 batches)
    const int bid = blockIdx.x;
    const int dir = bid >> 6;
    const int rr = bid & 63;
    const int bhalf = rr >> 5;
    const int ublk = rr & 31;
    const int tid = threadIdx.x;
    const int wid = tid >> 5, lane = tid & 31;
    const int u_base = ublk * 16 + wid * 2;
    const unsigned NB = gridDim.x;

    // Preload recurrent weights: wf[unit][gate][16], element c*4+q <-> k = c*128 + lane*4 + q
    float wf[2][3][16];
    float bhh[2][3];
    #pragma unroll
    for (int ul = 0; ul < 2; ul++)
        #pragma unroll
        for (int g = 0; g < 3; g++) {
            int row = g * HH + u_base + ul;
            const float4* wr = (const float4*)(w_hh + ((size_t)dir * G3 + row) * HH);
            #pragma unroll
            for (int c = 0; c < 4; c++) {
                float4 wv = __ldg(wr + c * 32 + lane);
                wf[ul][g][c*4+0]=wv.x; wf[ul][g][c*4+1]=wv.y;
                wf[ul][g][c*4+2]=wv.z; wf[ul][g][c*4+3]=wv.w;
            }
            bhh[ul][g] = __ldg(b_hh + dir * G3 + row);
        }

    // zero h[dir][buf0][:, :] (each CTA zeroes its (bhalf, ublk) slice)
    {
        float* z = g_h + (size_t)(dir * 2 + 0) * BB * HH;
        for (int i = tid; i < 32 * 16; i += 256) {
            int bl = i >> 4, uu = i & 15;
            z[(size_t)(bhalf * 32 + bl) * HH + ublk * 16 + uu] = 0.f;
        }
    }
    grid_sync(NB);

    for (int s = 0; s < TT; s++) {
        const int t = dir ? (TT - 1 - s) : s;
        const int bufo = s & 1;
        const int bufn = bufo ^ 1;

        // stage h_old[this CTA's 32 batches][512] (L2 reads: other CTAs wrote it)
        const float4* hsrc = (const float4*)(g_h + ((size_t)(dir * 2 + bufo) * BB + bhalf * 32) * HH);
        float4* hs4 = (float4*)hs;
        #pragma unroll
        for (int i = 0; i < 16; i++) {
            int idx = tid + i * 256;
            hs4[idx] = __ldcg(hsrc + idx);
        }
        __syncthreads();

        float sv[6] = {0.f, 0.f, 0.f, 0.f, 0.f, 0.f};
        for (int bl = 0; bl < 32; bl++) {
            const float4* hrow4 = (const float4*)(hs + bl * HH);
            float acc[2][3] = {};
            #pragma unroll
            for (int c = 0; c < 4; c++) {
                float4 hf = hrow4[c * 32 + lane];   // conflict-free: consecutive lanes, consecutive float4
                #pragma unroll
                for (int ul = 0; ul < 2; ul++)
                    #pragma unroll
                    for (int g = 0; g < 3; g++) {
                        acc[ul][g] = fmaf(wf[ul][g][c*4+0], hf.x, acc[ul][g]);
                        acc[ul][g] = fmaf(wf[ul][g][c*4+1], hf.y, acc[ul][g]);
                        acc[ul][g] = fmaf(wf[ul][g][c*4+2], hf.z, acc[ul][g]);
                        acc[ul][g] = fmaf(wf[ul][g][c*4+3], hf.w, acc[ul][g]);
                    }
            }
            #pragma unroll
            for (int off = 16; off; off >>= 1)
                #pragma unroll
                for (int ul = 0; ul < 2; ul++)
                    #pragma unroll
                    for (int g = 0; g < 3; g++)
                        acc[ul][g] += __shfl_xor_sync(0xffffffffu, acc[ul][g], off);
            if (lane == bl) {
                sv[0]=acc[0][0]; sv[1]=acc[0][1]; sv[2]=acc[0][2];
                sv[3]=acc[1][0]; sv[4]=acc[1][1]; sv[5]=acc[1][2];
            }
        }

        // gate math, vectorized over lanes (lane == local batch)
        {
            const int bglob = bhalf * 32 + lane;
            const float* xgb = g_xg + (((size_t)dir * TT + t) * BB + bglob) * G3;
            float* hnb = g_h + ((size_t)(dir * 2 + bufn) * BB + bglob) * HH;
            #pragma unroll
            for (int ul = 0; ul < 2; ul++) {
                int u = u_base + ul;
                float hr = sv[ul*3+0] + bhh[ul][0];
                float hz = sv[ul*3+1] + bhh[ul][1];
                float hn = sv[ul*3+2] + bhh[ul][2];
                float xr = __ldg(xgb + u);
                float xz = __ldg(xgb + HH + u);
                float xn = __ldg(xgb + 2 * HH + u);
                float rg = 1.f / (1.f + __expf(-(xr + hr)));
                float zg = 1.f / (1.f + __expf(-(xz + hz)));
                float ng = tanhf(xn + rg * hn);
                float hp = hs[lane * HH + u];
                float hv = (1.f - zg) * ng + zg * hp;
                hnb[u] = hv;
                if (layer == 0)
                    g_out0[((size_t)bglob * TT + t) * (2 * HH) + dir * HH + u] = hv;
            }
        }
        grid_sync(NB);
    }
}

// ---------------- FC head: out[b][c] = cat(hT_f, hT_b) . fc_w[c] + fc_b[c] -----
__global__ void fc_kernel(const float* __restrict__ fc_w, const float* __restrict__ fc_b,
                          float* __restrict__ out) {
    int b = blockIdx.x;
    int c = threadIdx.x >> 5;
    int lane = threadIdx.x & 31;
    // final state is in buf 0 (512 steps -> (511+1)&1 = 0)
    const float* hf = g_h + (size_t)b * HH;                            // dir0 buf0
    const float* hb = g_h + (size_t)2 * BB * HH + (size_t)b * HH;      // dir1 buf0
    const float* w = fc_w + c * (2 * HH);
    float s = 0.f;
    for (int k = lane; k < HH; k += 32) {
        s = fmaf(hf[k], w[k], s);
        s = fmaf(hb[k], w[HH + k], s);
    }
    #pragma unroll
    for (int off = 16; off; off >>= 1) s += __shfl_xor_sync(0xffffffffu, s, off);
    if (lane == 0) out[b * 10 + c] = s + fc_b[c];
}

// ---------------- launch ----------------
extern "C" void kernel_launch(void* const* d_in, const int* in_sizes, int n_in,
                              void* d_out, int out_size) {
    (void)in_sizes; (void)n_in; (void)out_size;
    const int*   sentence = (const int*)  d_in[0];
    const float* emb      = (const float*)d_in[1];
    const float* w_ih_l0  = (const float*)d_in[2];
    const float* w_hh_l0  = (const float*)d_in[3];
    const float* b_ih_l0  = (const float*)d_in[4];
    const float* b_hh_l0  = (const float*)d_in[5];
    const float* w_ih_l1  = (const float*)d_in[6];
    const float* w_hh_l1  = (const float*)d_in[7];
    const float* b_ih_l1  = (const float*)d_in[8];
    const float* b_hh_l1  = (const float*)d_in[9];
    const float* fc_w     = (const float*)d_in[10];
    const float* fc_b     = (const float*)d_in[11];
    float* out = (float*)d_out;

    // allow 64KB dynamic smem for the scan kernel (idempotent, not a stream op)
    cudaFuncSetAttribute(scan_kernel, cudaFuncAttributeMaxDynamicSharedMemorySize, 65536);

    embed_kernel<<<BB * TT, 64>>>(sentence, emb);

    // layer 0
    inproj_kernel<<<dim3((BB * TT) / 64, G3 / 64, 2), 256>>>(w_ih_l0, b_ih_l0, EE, 0);
    scan_kernel<<<128, 256, 65536>>>(w_hh_l0, b_hh_l0, 0);

    // layer 1
    inproj_kernel<<<dim3((BB * TT) / 64, G3 / 64, 2), 256>>>(w_ih_l1, b_ih_l1, 2 * HH, 1);
    scan_kernel<<<128, 256, 65536>>>(w_hh_l1, b_hh_l1, 1);

    fc_kernel<<<BB, 320>>>(fc_w, fc_b, out);
}

// round 5
// speedup vs baseline: 1.4514x; 1.4514x over previous
#include <cuda_runtime.h>
#include <math.h>

// Shapes (fixed by the problem)
#define BB 64      // batch
#define TT 512     // seq len
#define EE 256     // embed dim
#define HH 512     // hidden
#define G3 1536    // 3*H
#define HR 516     // padded smem row stride for h (floats): 4-way instead of 32-way conflict

typedef unsigned long long ull;

// ---------------- scratch (device globals; no allocation allowed) ------------
__device__ float g_x0[(size_t)BB * TT * EE];             // [B*T][256]   embeddings
__device__ float g_xg[(size_t)2 * TT * BB * G3];         // [dir][t][b][3H] input-gate proj
__device__ float g_out0[(size_t)BB * TT * 2 * HH];       // [b][t][2H]   layer-0 outputs
__device__ float g_h[(size_t)2 * 2 * BB * HH];           // [dir][buf][b][H] ping-pong state
__device__ unsigned g_cnt2[64];                          // per-dir barrier counters (sep lines)
__device__ volatile unsigned g_gen2[64];

// ---------------- f32x2 packed helpers ----------------
__device__ __forceinline__ ull f2pack(float x, float y) {
    ull r; asm("mov.b64 %0,{%1,%2};" : "=l"(r) : "f"(x), "f"(y)); return r;
}
__device__ __forceinline__ ull ffma2(ull a, ull b, ull c) {
    ull d; asm("fma.rn.f32x2 %0,%1,%2,%3;" : "=l"(d) : "l"(a), "l"(b), "l"(c)); return d;
}
__device__ __forceinline__ void f2unpack(ull p, float& x, float& y) {
    asm("mov.b64 {%0,%1},%2;" : "=f"(x), "=f"(y) : "l"(p));
}

// ---------------- per-direction software grid barrier (64 CTAs, co-resident)
__device__ __forceinline__ void dir_sync(int dir, unsigned nb) {
    __threadfence();
    __syncthreads();
    if (threadIdx.x == 0) {
        unsigned* cnt = &g_cnt2[dir * 32];
        unsigned my = g_gen2[dir * 32];
        if (atomicAdd(cnt, 1) == nb - 1) {
            atomicExch(cnt, 0);
            __threadfence();
            g_gen2[dir * 32] = my + 1;
        } else {
            while (g_gen2[dir * 32] == my) __nanosleep(32);
        }
    }
    __syncthreads();
    __threadfence();
}

// ---------------- embedding gather ----------------
__global__ void embed_kernel(const int* __restrict__ sent, const float* __restrict__ emb) {
    int row = blockIdx.x;                 // row = b*T + t
    int idx = sent[row];
    const float4* src = (const float4*)(emb + (size_t)idx * EE);
    float4* dst = (float4*)(g_x0 + (size_t)row * EE);
    dst[threadIdx.x] = src[threadIdx.x];  // 64 threads * float4 = 256 floats
}

// ---------------- input projection GEMM (f32x2) ------------------------------
// xg[dir][t][b][g] = A[b*T+t][:] . W[dir][g][:] + b_ih
// Tile 128x128, BK=16, 8x8 microtile, A duplicated in smem so (a,a) pairs are
// a single LDS.64; B pairs come free from consecutive layout. Double-buffered.
__global__ __launch_bounds__(256, 2) void inproj_kernel(const float* __restrict__ W,
                                                        const float* __restrict__ bias,
                                                        int K, int layer) {
    const float* A = (layer == 0) ? g_x0 : g_out0;
    __shared__ __align__(16) float sA[2][16][256];   // A duplicated: [k][2m],[2m+1]
    __shared__ __align__(16) float sB[2][16][128];

    const int m0 = blockIdx.x * 128, n0 = blockIdx.y * 128, dir = blockIdx.z;
    const float* Wd = W + (size_t)dir * G3 * K;
    const int tid = threadIdx.x;
    const int r = tid & 127;              // loader row within tile
    const int cb = (tid >> 7) * 2;        // loader float4-column base {0,2}
    const int ty = tid >> 4, tx = tid & 15;
    const float* Ar = A + (size_t)(m0 + r) * K;
    const float* Br = Wd + (size_t)(n0 + r) * K;

    ull acc[8][4];
    #pragma unroll
    for (int i = 0; i < 8; i++)
        #pragma unroll
        for (int j = 0; j < 4; j++) acc[i][j] = 0ull;

    // preload tile 0 into buf 0
    {
        float4 pa0 = *(const float4*)(Ar + cb * 4);
        float4 pa1 = *(const float4*)(Ar + cb * 4 + 4);
        float4 pb0 = *(const float4*)(Br + cb * 4);
        float4 pb1 = *(const float4*)(Br + cb * 4 + 4);
        float a0[4] = {pa0.x, pa0.y, pa0.z, pa0.w};
        float a1[4] = {pa1.x, pa1.y, pa1.z, pa1.w};
        float b0[4] = {pb0.x, pb0.y, pb0.z, pb0.w};
        float b1[4] = {pb1.x, pb1.y, pb1.z, pb1.w};
        #pragma unroll
        for (int e = 0; e < 4; e++) {
            sA[0][cb * 4 + e][2 * r] = a0[e];     sA[0][cb * 4 + e][2 * r + 1] = a0[e];
            sA[0][cb * 4 + 4 + e][2 * r] = a1[e]; sA[0][cb * 4 + 4 + e][2 * r + 1] = a1[e];
            sB[0][cb * 4 + e][r] = b0[e];
            sB[0][cb * 4 + 4 + e][r] = b1[e];
        }
    }
    __syncthreads();

    const int KT = K / 16;
    for (int kt = 0; kt < KT; kt++) {
        const int buf = kt & 1;
        float4 pa0, pa1, pb0, pb1;
        const bool more = (kt + 1 < KT);
        if (more) {
            const float* an = Ar + (kt + 1) * 16;
            const float* bn = Br + (kt + 1) * 16;
            pa0 = *(const float4*)(an + cb * 4);
            pa1 = *(const float4*)(an + cb * 4 + 4);
            pb0 = *(const float4*)(bn + cb * 4);
            pb1 = *(const float4*)(bn + cb * 4 + 4);
        }
        #pragma unroll
        for (int k = 0; k < 16; k++) {
            const ulonglong2* Ak = (const ulonglong2*)&sA[buf][k][0];
            const ulonglong2* Bk = (const ulonglong2*)&sB[buf][k][0];
            ulonglong2 d0 = Ak[ty * 4 + 0], d1 = Ak[ty * 4 + 1];
            ulonglong2 d2 = Ak[ty * 4 + 2], d3 = Ak[ty * 4 + 3];
            ulonglong2 e0 = Bk[tx * 2 + 0], e1 = Bk[tx * 2 + 1];
            ull da[8] = {d0.x, d0.y, d1.x, d1.y, d2.x, d2.y, d3.x, d3.y};
            ull db[4] = {e0.x, e0.y, e1.x, e1.y};
            #pragma unroll
            for (int i = 0; i < 8; i++)
                #pragma unroll
                for (int j = 0; j < 4; j++)
                    acc[i][j] = ffma2(da[i], db[j], acc[i][j]);
        }
        if (more) {
            const int nb = buf ^ 1;
            float a0[4] = {pa0.x, pa0.y, pa0.z, pa0.w};
            float a1[4] = {pa1.x, pa1.y, pa1.z, pa1.w};
            float b0[4] = {pb0.x, pb0.y, pb0.z, pb0.w};
            float b1[4] = {pb1.x, pb1.y, pb1.z, pb1.w};
            #pragma unroll
            for (int e = 0; e < 4; e++) {
                sA[nb][cb * 4 + e][2 * r] = a0[e];     sA[nb][cb * 4 + e][2 * r + 1] = a0[e];
                sA[nb][cb * 4 + 4 + e][2 * r] = a1[e]; sA[nb][cb * 4 + 4 + e][2 * r + 1] = a1[e];
                sB[nb][cb * 4 + e][r] = b0[e];
                sB[nb][cb * 4 + 4 + e][r] = b1[e];
            }
        }
        __syncthreads();
    }

    // epilogue: +bias, scatter into g_xg[dir][t][b][3H]
    const float* bp = bias + dir * G3 + n0 + tx * 8;
    float4 bv0 = *(const float4*)bp;
    float4 bv1 = *(const float4*)(bp + 4);
    #pragma unroll
    for (int i = 0; i < 8; i++) {
        int m = m0 + ty * 8 + i;
        int b_ = m >> 9, t_ = m & 511;       // m = b*512 + t (tile never crosses b)
        float* dst = g_xg + (((size_t)dir * TT + t_) * BB + b_) * G3 + n0 + tx * 8;
        float x, y; float4 o0, o1;
        f2unpack(acc[i][0], x, y); o0.x = x + bv0.x; o0.y = y + bv0.y;
        f2unpack(acc[i][1], x, y); o0.z = x + bv0.z; o0.w = y + bv0.w;
        f2unpack(acc[i][2], x, y); o1.x = x + bv1.x; o1.y = y + bv1.y;
        f2unpack(acc[i][3], x, y); o1.z = x + bv1.z; o1.w = y + bv1.w;
        *(float4*)dst = o0;
        *(float4*)(dst + 4) = o1;
    }
}

// ---------------- persistent GRU scan (one launch per layer) ----------------
// grid = 128 CTAs: dir(2) x bhalf(2: 32 batches) x ublk(32: 16 units).
// warp w -> 2 units (6 w_hh rows as f32x2 pairs, register-resident all 512 steps).
// Batch pairs (p, p+16) reduced through one shared butterfly tree.
__global__ __launch_bounds__(256, 1) void scan_kernel(const float* __restrict__ w_hh,
                                                      const float* __restrict__ b_hh,
                                                      int layer) {
    extern __shared__ float hs[];  // [32][HR] staged h_old (this CTA's 32 batches)
    const int bid = blockIdx.x;
    const int dir = bid >> 6;
    const int rr = bid & 63;
    const int bhalf = rr >> 5;
    const int ublk = rr & 31;
    const int tid = threadIdx.x;
    const int wid = tid >> 5, lane = tid & 31;
    const int u_base = ublk * 16 + wid * 2;

    // Preload recurrent weights as f32x2 pairs: row r=ul*3+g, pair c*2+q <-> k=c*128+lane*4+2q
    ull wf2[6][8];
    float bhh[6];
    #pragma unroll
    for (int ul = 0; ul < 2; ul++)
        #pragma unroll
        for (int g = 0; g < 3; g++) {
            int row = g * HH + u_base + ul;
            const float4* wr = (const float4*)(w_hh + ((size_t)dir * G3 + row) * HH);
            #pragma unroll
            for (int c = 0; c < 4; c++) {
                float4 wv = __ldg(wr + c * 32 + lane);
                wf2[ul * 3 + g][c * 2 + 0] = f2pack(wv.x, wv.y);
                wf2[ul * 3 + g][c * 2 + 1] = f2pack(wv.z, wv.w);
            }
            bhh[ul * 3 + g] = __ldg(b_hh + dir * G3 + row);
        }

    // zero h[dir][buf0] slice
    {
        float* z = g_h + (size_t)(dir * 2 + 0) * BB * HH;
        for (int i = tid; i < 32 * 16; i += 256) {
            int bl = i >> 4, uu = i & 15;
            z[(size_t)(bhalf * 32 + bl) * HH + ublk * 16 + uu] = 0.f;
        }
    }
    dir_sync(dir, 64);

    const int bglob = bhalf * 32 + lane;
    for (int s = 0; s < TT; s++) {
        const int t = dir ? (TT - 1 - s) : s;
        const int bufo = s & 1;
        const int bufn = bufo ^ 1;

        // prefetch this step's xg gate inputs (latency hidden behind FMA phase)
        const float* xgb = g_xg + (((size_t)dir * TT + t) * BB + bglob) * G3;
        float xr0 = __ldg(xgb + u_base),          xr1 = __ldg(xgb + u_base + 1);
        float xz0 = __ldg(xgb + HH + u_base),     xz1 = __ldg(xgb + HH + u_base + 1);
        float xn0 = __ldg(xgb + 2 * HH + u_base), xn1 = __ldg(xgb + 2 * HH + u_base + 1);

        // stage h_old[32 batches][512] into padded smem (L2 reads; L1 must be bypassed)
        {
            const float4* hsrc = (const float4*)(g_h + ((size_t)(dir * 2 + bufo) * BB + bhalf * 32) * HH);
            float4* hs4 = (float4*)hs;
            #pragma unroll
            for (int p = 0; p < 16; p++) {
                int idx = tid + p * 256;
                int b = idx >> 7, c = idx & 127;
                hs4[(size_t)b * (HR / 4) + c] = __ldcg(hsrc + idx);
            }
        }
        __syncthreads();

        float sv[6];
        #pragma unroll 1
        for (int p = 0; p < 16; p++) {          // batch pair (p, p+16)
            const float4* hA = (const float4*)(hs + (size_t)p * HR);
            const float4* hB = (const float4*)(hs + (size_t)(p + 16) * HR);
            ull aA[6], aB[6];
            #pragma unroll
            for (int rI = 0; rI < 6; rI++) { aA[rI] = 0ull; aB[rI] = 0ull; }
            #pragma unroll
            for (int c = 0; c < 4; c++) {
                float4 va = hA[c * 32 + lane];   // conflict-free
                float4 vb = hB[c * 32 + lane];
                ull a01 = f2pack(va.x, va.y), a23 = f2pack(va.z, va.w);
                ull b01 = f2pack(vb.x, vb.y), b23 = f2pack(vb.z, vb.w);
                #pragma unroll
                for (int rI = 0; rI < 6; rI++) {
                    aA[rI] = ffma2(wf2[rI][c * 2 + 0], a01, aA[rI]);
                    aA[rI] = ffma2(wf2[rI][c * 2 + 1], a23, aA[rI]);
                    aB[rI] = ffma2(wf2[rI][c * 2 + 0], b01, aB[rI]);
                    aB[rI] = ffma2(wf2[rI][c * 2 + 1], b23, aB[rI]);
                }
            }
            const bool mine = (lane & 15) == p;
            #pragma unroll
            for (int rI = 0; rI < 6; rI++) {
                float x, y, la, lb;
                f2unpack(aA[rI], x, y); la = x + y;
                f2unpack(aB[rI], x, y); lb = x + y;
                float fa = la + __shfl_xor_sync(0xffffffffu, la, 16);
                float fb = lb + __shfl_xor_sync(0xffffffffu, lb, 16);
                float ts = (lane < 16) ? fa : fb;
                ts += __shfl_xor_sync(0xffffffffu, ts, 8);
                ts += __shfl_xor_sync(0xffffffffu, ts, 4);
                ts += __shfl_xor_sync(0xffffffffu, ts, 2);
                ts += __shfl_xor_sync(0xffffffffu, ts, 1);
                if (mine) sv[rI] = ts;           // lane p <- sum(A), lane p+16 <- sum(B)
            }
        }

        // gate math (lane == local batch)
        {
            float* hnb = g_h + ((size_t)(dir * 2 + bufn) * BB + bglob) * HH;
            // unit 0
            {
                float hr = sv[0] + bhh[0], hz = sv[1] + bhh[1], hn = sv[2] + bhh[2];
                float rg = 1.f / (1.f + __expf(-(xr0 + hr)));
                float zg = 1.f / (1.f + __expf(-(xz0 + hz)));
                float ng = tanhf(xn0 + rg * hn);
                float hp = hs[(size_t)lane * HR + u_base];
                float hv = (1.f - zg) * ng + zg * hp;
                hnb[u_base] = hv;
                if (layer == 0)
                    g_out0[((size_t)bglob * TT + t) * (2 * HH) + dir * HH + u_base] = hv;
            }
            // unit 1
            {
                float hr = sv[3] + bhh[3], hz = sv[4] + bhh[4], hn = sv[5] + bhh[5];
                float rg = 1.f / (1.f + __expf(-(xr1 + hr)));
                float zg = 1.f / (1.f + __expf(-(xz1 + hz)));
                float ng = tanhf(xn1 + rg * hn);
                float hp = hs[(size_t)lane * HR + u_base + 1];
                float hv = (1.f - zg) * ng + zg * hp;
                hnb[u_base + 1] = hv;
                if (layer == 0)
                    g_out0[((size_t)bglob * TT + t) * (2 * HH) + dir * HH + u_base + 1] = hv;
            }
        }
        dir_sync(dir, 64);
    }
}

// ---------------- FC head: out[b][c] = cat(hT_f, hT_b) . fc_w[c] + fc_b[c] -----
__global__ void fc_kernel(const float* __restrict__ fc_w, const float* __restrict__ fc_b,
                          float* __restrict__ out) {
    int b = blockIdx.x;
    int c = threadIdx.x >> 5;
    int lane = threadIdx.x & 31;
    // final state lands in buf 0 after 512 steps
    const float* hf = g_h + (size_t)b * HH;                            // dir0 buf0
    const float* hb = g_h + (size_t)2 * BB * HH + (size_t)b * HH;      // dir1 buf0
    const float* w = fc_w + c * (2 * HH);
    float s = 0.f;
    for (int k = lane; k < HH; k += 32) {
        s = fmaf(hf[k], w[k], s);
        s = fmaf(hb[k], w[HH + k], s);
    }
    #pragma unroll
    for (int off = 16; off; off >>= 1) s += __shfl_xor_sync(0xffffffffu, s, off);
    if (lane == 0) out[b * 10 + c] = s + fc_b[c];
}

// ---------------- launch ----------------
extern "C" void kernel_launch(void* const* d_in, const int* in_sizes, int n_in,
                              void* d_out, int out_size) {
    (void)in_sizes; (void)n_in; (void)out_size;
    const int*   sentence = (const int*)  d_in[0];
    const float* emb      = (const float*)d_in[1];
    const float* w_ih_l0  = (const float*)d_in[2];
    const float* w_hh_l0  = (const float*)d_in[3];
    const float* b_ih_l0  = (const float*)d_in[4];
    const float* b_hh_l0  = (const float*)d_in[5];
    const float* w_ih_l1  = (const float*)d_in[6];
    const float* w_hh_l1  = (const float*)d_in[7];
    const float* b_ih_l1  = (const float*)d_in[8];
    const float* b_hh_l1  = (const float*)d_in[9];
    const float* fc_w     = (const float*)d_in[10];
    const float* fc_b     = (const float*)d_in[11];
    float* out = (float*)d_out;

    const int SCAN_SMEM = 32 * HR * 4;   // 66048 bytes (padded rows)
    cudaFuncSetAttribute(scan_kernel, cudaFuncAttributeMaxDynamicSharedMemorySize, SCAN_SMEM);

    embed_kernel<<<BB * TT, 64>>>(sentence, emb);

    // layer 0
    inproj_kernel<<<dim3((BB * TT) / 128, G3 / 128, 2), 256>>>(w_ih_l0, b_ih_l0, EE, 0);
    scan_kernel<<<128, 256, SCAN_SMEM>>>(w_hh_l0, b_hh_l0, 0);

    // layer 1
    inproj_kernel<<<dim3((BB * TT) / 128, G3 / 128, 2), 256>>>(w_ih_l1, b_ih_l1, 2 * HH, 1);
    scan_kernel<<<128, 256, SCAN_SMEM>>>(w_hh_l1, b_hh_l1, 1);

    fc_kernel<<<BB, 320>>>(fc_w, fc_b, out);
}

// round 6
// speedup vs baseline: 1.7487x; 1.2048x over previous
#include <cuda_runtime.h>
#include <math.h>

// Shapes (fixed by the problem)
#define BB 64      // batch
#define TT 512     // seq len
#define EE 256     // embed dim
#define HH 512     // hidden
#define G3 1536    // 3*H
#define HR 516     // padded smem row stride for h (floats)
#define SMS 132    // padded GEMM smem row stride (floats)

typedef unsigned long long ull;

// ---------------- scratch (device globals; no allocation allowed) ------------
__device__ float g_x0[(size_t)BB * TT * EE];             // [B*T][256]   embeddings
__device__ float g_xg[(size_t)2 * TT * BB * G3];         // [dir][t][b][3H] input-gate proj
__device__ float g_out0[(size_t)BB * TT * 2 * HH];       // [b][t][2H]   layer-0 outputs
__device__ float g_h[(size_t)2 * 2 * BB * HH];           // [dir][buf][b][H] ping-pong state
__device__ unsigned g_cnt[128];                          // per-group barrier counters
__device__ volatile unsigned g_gen[128];

// ---------------- f32x2 packed helpers ----------------
__device__ __forceinline__ ull f2pack(float x, float y) {
    ull r; asm("mov.b64 %0,{%1,%2};" : "=l"(r) : "f"(x), "f"(y)); return r;
}
__device__ __forceinline__ ull ffma2(ull a, ull b, ull c) {
    ull d; asm("fma.rn.f32x2 %0,%1,%2,%3;" : "=l"(d) : "l"(a), "l"(b), "l"(c)); return d;
}
__device__ __forceinline__ void f2unpack(ull p, float& x, float& y) {
    asm("mov.b64 {%0,%1},%2;" : "=f"(x), "=f"(y) : "l"(p));
}

// ---------------- per-(dir,bhalf) software grid barrier (32 CTAs each) -------
__device__ __forceinline__ void grp_sync(int gid) {
    __threadfence();
    __syncthreads();
    if (threadIdx.x == 0) {
        unsigned* cnt = &g_cnt[gid * 32];
        volatile unsigned* gen = &g_gen[gid * 32];
        unsigned my = *gen;
        if (atomicAdd(cnt, 1) == 31) {
            atomicExch(cnt, 0);
            __threadfence();
            *gen = my + 1;
        } else {
            while (*gen == my) { }
        }
    }
    __syncthreads();
    __threadfence();
}

// ---------------- embedding gather ----------------
__global__ void embed_kernel(const int* __restrict__ sent, const float* __restrict__ emb) {
    int row = blockIdx.x;                 // row = b*T + t
    int idx = sent[row];
    const float4* src = (const float4*)(emb + (size_t)idx * EE);
    float4* dst = (float4*)(g_x0 + (size_t)row * EE);
    dst[threadIdx.x] = src[threadIdx.x];  // 64 threads * float4 = 256 floats
}

// ---------------- input projection GEMM (f32x2, A-pairs x dup-B) -------------
// xg[dir][t][b][g] = A[b*T+t][:] . W[dir][g][:] + b_ih
// Tile 128x128, BK=16, 8x8 microtile. A pairs come free from consecutive smem
// (M-pairs, LDS.128); B scalars duplicated in registers (mov.b64 {b,b}).
__global__ __launch_bounds__(256, 2) void inproj_kernel(const float* __restrict__ W,
                                                        const float* __restrict__ bias,
                                                        int K, int layer) {
    const float* A = (layer == 0) ? g_x0 : g_out0;
    __shared__ __align__(16) float sA[2][16][SMS];
    __shared__ __align__(16) float sB[2][16][SMS];

    const int m0 = blockIdx.x * 128, n0 = blockIdx.y * 128, dir = blockIdx.z;
    const float* Wd = W + (size_t)dir * G3 * K;
    const int tid = threadIdx.x;
    const int lr = tid >> 2, lc = tid & 3;     // loader: 64 rows x 4 float4-cols (coalesced)
    const int ty = tid >> 4, tx = tid & 15;    // compute: 16x16 threads, 8x8 outputs
    const float* Ar0 = A + (size_t)(m0 + lr) * K + lc * 4;
    const float* Ar1 = A + (size_t)(m0 + lr + 64) * K + lc * 4;
    const float* Br0 = Wd + (size_t)(n0 + lr) * K + lc * 4;
    const float* Br1 = Wd + (size_t)(n0 + lr + 64) * K + lc * 4;

    ull acc[4][8];
    #pragma unroll
    for (int i = 0; i < 4; i++)
        #pragma unroll
        for (int j = 0; j < 8; j++) acc[i][j] = 0ull;

    // preload tile 0 into buf 0
    {
        float4 a0 = *(const float4*)Ar0;
        float4 a1 = *(const float4*)Ar1;
        float4 b0 = *(const float4*)Br0;
        float4 b1 = *(const float4*)Br1;
        float av0[4] = {a0.x, a0.y, a0.z, a0.w}, av1[4] = {a1.x, a1.y, a1.z, a1.w};
        float bv0[4] = {b0.x, b0.y, b0.z, b0.w}, bv1[4] = {b1.x, b1.y, b1.z, b1.w};
        #pragma unroll
        for (int e = 0; e < 4; e++) {
            sA[0][lc * 4 + e][lr] = av0[e];  sA[0][lc * 4 + e][lr + 64] = av1[e];
            sB[0][lc * 4 + e][lr] = bv0[e];  sB[0][lc * 4 + e][lr + 64] = bv1[e];
        }
    }
    __syncthreads();

    const int KT = K / 16;
    for (int kt = 0; kt < KT; kt++) {
        const int buf = kt & 1;
        float4 a0, a1, b0, b1;
        const bool more = (kt + 1 < KT);
        if (more) {
            a0 = *(const float4*)(Ar0 + (kt + 1) * 16);
            a1 = *(const float4*)(Ar1 + (kt + 1) * 16);
            b0 = *(const float4*)(Br0 + (kt + 1) * 16);
            b1 = *(const float4*)(Br1 + (kt + 1) * 16);
        }
        #pragma unroll
        for (int k = 0; k < 16; k++) {
            const ulonglong2* Ak = (const ulonglong2*)&sA[buf][k][ty * 8];
            ulonglong2 aa = Ak[0], ab = Ak[1];                 // 4 M-pairs
            ull ap[4] = {aa.x, aa.y, ab.x, ab.y};
            const float4* Bk = (const float4*)&sB[buf][k][tx * 8];
            float4 b03 = Bk[0], b47 = Bk[1];
            ull bd[8];
            bd[0] = f2pack(b03.x, b03.x); bd[1] = f2pack(b03.y, b03.y);
            bd[2] = f2pack(b03.z, b03.z); bd[3] = f2pack(b03.w, b03.w);
            bd[4] = f2pack(b47.x, b47.x); bd[5] = f2pack(b47.y, b47.y);
            bd[6] = f2pack(b47.z, b47.z); bd[7] = f2pack(b47.w, b47.w);
            #pragma unroll
            for (int i = 0; i < 4; i++)
                #pragma unroll
                for (int j = 0; j < 8; j++)
                    acc[i][j] = ffma2(ap[i], bd[j], acc[i][j]);
        }
        if (more) {
            const int nb = buf ^ 1;
            float av0[4] = {a0.x, a0.y, a0.z, a0.w}, av1[4] = {a1.x, a1.y, a1.z, a1.w};
            float bv0[4] = {b0.x, b0.y, b0.z, b0.w}, bv1[4] = {b1.x, b1.y, b1.z, b1.w};
            #pragma unroll
            for (int e = 0; e < 4; e++) {
                sA[nb][lc * 4 + e][lr] = av0[e];  sA[nb][lc * 4 + e][lr + 64] = av1[e];
                sB[nb][lc * 4 + e][lr] = bv0[e];  sB[nb][lc * 4 + e][lr + 64] = bv1[e];
            }
        }
        __syncthreads();
    }

    // epilogue: +bias, scatter into g_xg[dir][t][b][3H]
    const int nv = n0 + tx * 8;
    const float* bp = bias + dir * G3 + nv;
    float4 bb0 = *(const float4*)bp;
    float4 bb1 = *(const float4*)(bp + 4);
    float bsv[8] = {bb0.x, bb0.y, bb0.z, bb0.w, bb1.x, bb1.y, bb1.z, bb1.w};
    #pragma unroll
    for (int i = 0; i < 4; i++) {
        float lo[8], hi[8];
        #pragma unroll
        for (int j = 0; j < 8; j++) f2unpack(acc[i][j], lo[j], hi[j]);
        int m = m0 + ty * 8 + 2 * i;
        #pragma unroll
        for (int h = 0; h < 2; h++) {
            int mm = m + h;
            int b_ = mm >> 9, t_ = mm & 511;        // m = b*512 + t
            float* dst = g_xg + (((size_t)dir * TT + t_) * BB + b_) * G3 + nv;
            const float* v = h ? hi : lo;
            float4 o0, o1;
            o0.x = v[0] + bsv[0]; o0.y = v[1] + bsv[1]; o0.z = v[2] + bsv[2]; o0.w = v[3] + bsv[3];
            o1.x = v[4] + bsv[4]; o1.y = v[5] + bsv[5]; o1.z = v[6] + bsv[6]; o1.w = v[7] + bsv[7];
            *(float4*)dst = o0;
            *(float4*)(dst + 4) = o1;
        }
    }
}

// ---------------- persistent GRU scan (one launch per layer) ----------------
// grid = 128 CTAs: dir(2) x bhalf(2: 32 batches) x ublk(32: 16 units).
// warp w -> 2 units (6 w_hh rows as f32x2 pairs, register-resident all 512 steps).
// Batch quads {g, g+8, g+16, g+24} reduced through one shared butterfly tree.
// Sync group = 32 CTAs sharing (dir, bhalf) — the only CTAs exchanging h.
__global__ __launch_bounds__(256, 1) void scan_kernel(const float* __restrict__ w_hh,
                                                      const float* __restrict__ b_hh,
                                                      int layer) {
    extern __shared__ float hs[];  // [32][HR] staged h_old (this CTA's 32 batches)
    const int bid = blockIdx.x;
    const int dir = bid >> 6;
    const int rr = bid & 63;
    const int bhalf = rr >> 5;
    const int ublk = rr & 31;
    const int gid = dir * 2 + bhalf;       // barrier group (32 CTAs)
    const int tid = threadIdx.x;
    const int wid = tid >> 5, lane = tid & 31;
    const int u_base = ublk * 16 + wid * 2;

    // Preload recurrent weights as f32x2 pairs: row r=ul*3+g, pair c*2+q <-> k=c*128+lane*4+2q
    ull wf2[6][8];
    float bhh[6];
    #pragma unroll
    for (int ul = 0; ul < 2; ul++)
        #pragma unroll
        for (int g = 0; g < 3; g++) {
            int row = g * HH + u_base + ul;
            const float4* wr = (const float4*)(w_hh + ((size_t)dir * G3 + row) * HH);
            #pragma unroll
            for (int c = 0; c < 4; c++) {
                float4 wv = __ldg(wr + c * 32 + lane);
                wf2[ul * 3 + g][c * 2 + 0] = f2pack(wv.x, wv.y);
                wf2[ul * 3 + g][c * 2 + 1] = f2pack(wv.z, wv.w);
            }
            bhh[ul * 3 + g] = __ldg(b_hh + dir * G3 + row);
        }

    // zero h[dir][buf0] slice
    {
        float* z = g_h + (size_t)(dir * 2 + 0) * BB * HH;
        for (int i = tid; i < 32 * 16; i += 256) {
            int bl = i >> 4, uu = i & 15;
            z[(size_t)(bhalf * 32 + bl) * HH + ublk * 16 + uu] = 0.f;
        }
    }
    grp_sync(gid);

    const int bglob = bhalf * 32 + lane;
    for (int s = 0; s < TT; s++) {
        const int t = dir ? (TT - 1 - s) : s;
        const int bufo = s & 1;
        const int bufn = bufo ^ 1;

        // prefetch this step's xg gate inputs (units u_base, u_base+1 consecutive)
        const float* xgb = g_xg + (((size_t)dir * TT + t) * BB + bglob) * G3;
        float2 xr = __ldg((const float2*)(xgb + u_base));
        float2 xz = __ldg((const float2*)(xgb + HH + u_base));
        float2 xn = __ldg((const float2*)(xgb + 2 * HH + u_base));

        // stage h_old[32 batches][512] into padded smem (L2 reads, bypass L1)
        {
            const float4* hsrc = (const float4*)(g_h + ((size_t)(dir * 2 + bufo) * BB + bhalf * 32) * HH);
            float4* hs4 = (float4*)hs;
            #pragma unroll
            for (int p = 0; p < 16; p++) {
                int idx = tid + p * 256;
                int b = idx >> 7, c = idx & 127;
                hs4[(size_t)b * (HR / 4) + c] = __ldcg(hsrc + idx);
            }
        }
        __syncthreads();

        float sv[6];
        #pragma unroll 1
        for (int g = 0; g < 8; g++) {       // batch quad {g, g+8, g+16, g+24}
            const ulonglong2* hA = (const ulonglong2*)(hs + (size_t)(g)      * HR);
            const ulonglong2* hC = (const ulonglong2*)(hs + (size_t)(g + 8)  * HR);
            const ulonglong2* hB = (const ulonglong2*)(hs + (size_t)(g + 16) * HR);
            const ulonglong2* hD = (const ulonglong2*)(hs + (size_t)(g + 24) * HR);
            ull aA[6], aB[6], aC[6], aD[6];
            #pragma unroll
            for (int rI = 0; rI < 6; rI++) { aA[rI]=0ull; aB[rI]=0ull; aC[rI]=0ull; aD[rI]=0ull; }
            #pragma unroll
            for (int c = 0; c < 4; c++) {
                ulonglong2 vA = hA[c * 32 + lane];   // float2 in smem IS a packed f32x2
                ulonglong2 vB = hB[c * 32 + lane];
                ulonglong2 vC = hC[c * 32 + lane];
                ulonglong2 vD = hD[c * 32 + lane];
                #pragma unroll
                for (int rI = 0; rI < 6; rI++) {
                    ull w0 = wf2[rI][c * 2], w1 = wf2[rI][c * 2 + 1];
                    aA[rI] = ffma2(w0, vA.x, aA[rI]); aA[rI] = ffma2(w1, vA.y, aA[rI]);
                    aB[rI] = ffma2(w0, vB.x, aB[rI]); aB[rI] = ffma2(w1, vB.y, aB[rI]);
                    aC[rI] = ffma2(w0, vC.x, aC[rI]); aC[rI] = ffma2(w1, vC.y, aC[rI]);
                    aD[rI] = ffma2(w0, vD.x, aD[rI]); aD[rI] = ffma2(w1, vD.y, aD[rI]);
                }
            }
            const bool mine = (lane & 7) == g;
            #pragma unroll
            for (int rI = 0; rI < 6; rI++) {
                float x, y;
                f2unpack(aA[rI], x, y); float vA_ = x + y;
                f2unpack(aB[rI], x, y); float vB_ = x + y;
                f2unpack(aC[rI], x, y); float vC_ = x + y;
                f2unpack(aD[rI], x, y); float vD_ = x + y;
                float fA = vA_ + __shfl_xor_sync(0xffffffffu, vA_, 16);
                float fB = vB_ + __shfl_xor_sync(0xffffffffu, vB_, 16);
                float fC = vC_ + __shfl_xor_sync(0xffffffffu, vC_, 16);
                float fD = vD_ + __shfl_xor_sync(0xffffffffu, vD_, 16);
                float xx = (lane & 16) ? fB : fA;     // quadrant (bit16,bit8): A,B,C,D
                float yy = (lane & 16) ? fD : fC;
                float fx = xx + __shfl_xor_sync(0xffffffffu, xx, 8);
                float fy = yy + __shfl_xor_sync(0xffffffffu, yy, 8);
                float z = (lane & 8) ? fy : fx;
                z += __shfl_xor_sync(0xffffffffu, z, 4);
                z += __shfl_xor_sync(0xffffffffu, z, 2);
                z += __shfl_xor_sync(0xffffffffu, z, 1);
                if (mine) sv[rI] = z;                 // lane g+8m <- its batch's sum
            }
        }

        // gate math (lane == local batch)
        {
            float* hnb = g_h + ((size_t)(dir * 2 + bufn) * BB + bglob) * HH;
            float xrv[2] = {xr.x, xr.y}, xzv[2] = {xz.x, xz.y}, xnv[2] = {xn.x, xn.y};
            #pragma unroll
            for (int ul = 0; ul < 2; ul++) {
                int u = u_base + ul;
                float hr = sv[ul * 3 + 0] + bhh[ul * 3 + 0];
                float hz = sv[ul * 3 + 1] + bhh[ul * 3 + 1];
                float hn = sv[ul * 3 + 2] + bhh[ul * 3 + 2];
                float rg = 1.f / (1.f + __expf(-(xrv[ul] + hr)));
                float zg = 1.f / (1.f + __expf(-(xzv[ul] + hz)));
                float ng = tanhf(xnv[ul] + rg * hn);
                float hp = hs[(size_t)lane * HR + u];
                float hv = (1.f - zg) * ng + zg * hp;
                hnb[u] = hv;
                if (layer == 0)
                    g_out0[((size_t)bglob * TT + t) * (2 * HH) + dir * HH + u] = hv;
            }
        }
        grp_sync(gid);
    }
}

// ---------------- FC head: out[b][c] = cat(hT_f, hT_b) . fc_w[c] + fc_b[c] -----
__global__ void fc_kernel(const float* __restrict__ fc_w, const float* __restrict__ fc_b,
                          float* __restrict__ out) {
    int b = blockIdx.x;
    int c = threadIdx.x >> 5;
    int lane = threadIdx.x & 31;
    // final state lands in buf 0 after 512 steps
    const float* hf = g_h + (size_t)b * HH;                            // dir0 buf0
    const float* hb = g_h + (size_t)2 * BB * HH + (size_t)b * HH;      // dir1 buf0
    const float* w = fc_w + c * (2 * HH);
    float s = 0.f;
    for (int k = lane; k < HH; k += 32) {
        s = fmaf(hf[k], w[k], s);
        s = fmaf(hb[k], w[HH + k], s);
    }
    #pragma unroll
    for (int off = 16; off; off >>= 1) s += __shfl_xor_sync(0xffffffffu, s, off);
    if (lane == 0) out[b * 10 + c] = s + fc_b[c];
}

// ---------------- launch ----------------
extern "C" void kernel_launch(void* const* d_in, const int* in_sizes, int n_in,
                              void* d_out, int out_size) {
    (void)in_sizes; (void)n_in; (void)out_size;
    const int*   sentence = (const int*)  d_in[0];
    const float* emb      = (const float*)d_in[1];
    const float* w_ih_l0  = (const float*)d_in[2];
    const float* w_hh_l0  = (const float*)d_in[3];
    const float* b_ih_l0  = (const float*)d_in[4];
    const float* b_hh_l0  = (const float*)d_in[5];
    const float* w_ih_l1  = (const float*)d_in[6];
    const float* w_hh_l1  = (const float*)d_in[7];
    const float* b_ih_l1  = (const float*)d_in[8];
    const float* b_hh_l1  = (const float*)d_in[9];
    const float* fc_w     = (const float*)d_in[10];
    const float* fc_b     = (const float*)d_in[11];
    float* out = (float*)d_out;

    const int SCAN_SMEM = 32 * HR * 4;   // 66048 bytes (padded rows)
    cudaFuncSetAttribute(scan_kernel, cudaFuncAttributeMaxDynamicSharedMemorySize, SCAN_SMEM);

    embed_kernel<<<BB * TT, 64>>>(sentence, emb);

    // layer 0
    inproj_kernel<<<dim3((BB * TT) / 128, G3 / 128, 2), 256>>>(w_ih_l0, b_ih_l0, EE, 0);
    scan_kernel<<<128, 256, SCAN_SMEM>>>(w_hh_l0, b_hh_l0, 0);

    // layer 1
    inproj_kernel<<<dim3((BB * TT) / 128, G3 / 128, 2), 256>>>(w_ih_l1, b_ih_l1, 2 * HH, 1);
    scan_kernel<<<128, 256, SCAN_SMEM>>>(w_hh_l1, b_hh_l1, 1);

    fc_kernel<<<BB, 320>>>(fc_w, fc_b, out);
}